// round 8
// baseline (speedup 1.0000x reference)
#include <cuda_runtime.h>
#include <cuda_fp16.h>

// ---------------------------------------------------------------------------
// GNNEncoder: 2-layer GCN. out[d] = dinv[d]*sum_{(s,d)}(x[s]@W)*dinv[s] + b
// R8: the single-block scan (measured 103us, half the runtime!) replaced by
//     a 3-phase hierarchical scan (part -> warp-scan -> expand, ~15us).
//     Everything else kept from R7: gemm1 overlapped with CSR build via
//     forked capture branch; FFMA2 register-tiled GEMM; fp16 gather agg.
// All scratch in __device__ globals; graph-capturable (kernels + events only).
// ---------------------------------------------------------------------------

#define NODES_MAX 50000
#define EDGES_MAX 800000
#define NPART     1024

__device__ int    g_odd_or;                 // !=0 => edge_index is int32
__device__ int    g_cnt[NODES_MAX];
__device__ int    g_off[NODES_MAX + 1];
__device__ int    g_cursor[NODES_MAX];
__device__ int    g_csr_src[EDGES_MAX];
__device__ int    g_part[NPART];
__device__ float  g_dinv[NODES_MAX];
__device__ __half g_hs [NODES_MAX * 128];   // layer1 x@W1          (gathered)
__device__ float  g_x2 [NODES_MAX * 128];   // layer1 output (post relu)
__device__ __half g_hs2[NODES_MAX * 64];    // layer2 x2@W2         (gathered)

// ---- side stream for forked capture branch --------------------------------
namespace {
struct SideStream {
    cudaStream_t s2 = nullptr;
    cudaEvent_t  fork = nullptr, joinB = nullptr;
    bool ok = false;
    SideStream()
    {
        ok = (cudaStreamCreateWithFlags(&s2, cudaStreamNonBlocking) == cudaSuccess) &&
             (cudaEventCreateWithFlags(&fork, cudaEventDisableTiming) == cudaSuccess) &&
             (cudaEventCreateWithFlags(&joinB, cudaEventDisableTiming) == cudaSuccess);
    }
};
SideStream g_ss;
}

// ---- f32x2 helpers --------------------------------------------------------
__device__ __forceinline__ unsigned long long pack2(float lo, float hi)
{
    unsigned long long r;
    asm("mov.b64 %0, {%1, %2};" : "=l"(r) : "f"(lo), "f"(hi));
    return r;
}
__device__ __forceinline__ void unpack2(unsigned long long v, float& lo, float& hi)
{
    asm("mov.b64 {%0, %1}, %2;" : "=f"(lo), "=f"(hi) : "l"(v));
}
__device__ __forceinline__ void ffma2(unsigned long long& d,
                                      unsigned long long a,
                                      unsigned long long b)
{
    asm("fma.rn.f32x2 %0, %1, %2, %3;" : "=l"(d) : "l"(a), "l"(b), "l"(d));
}

// smem anti-conflict swizzle: insert a 2-entry (16B) gap every 16 entries.
__device__ __forceinline__ int swz(int i) { return i + ((i >> 4) << 1); }

// ---- CSR build --------------------------------------------------------------
__global__ void k_init(const int* __restrict__ v, int N)
{
    int i = blockIdx.x * blockDim.x + threadIdx.x;
    if (i < N) g_cnt[i] = 0;
    if (i == 0) g_odd_or = 0;
    // dtype detect: int64 viewed as int32 pairs -> odd words all zero.
    if (i < 256 && v[2 * i + 1] != 0) atomicOr(&g_odd_or, 1);
}

__global__ void k_hist(const int* __restrict__ v, int E, int N)
{
    int base = (blockIdx.x * blockDim.x + threadIdx.x) * 4;
    if (base >= E) return;
    int is32 = g_odd_or;
    if (base + 4 <= E) {
        unsigned d0, d1, d2, d3;
        if (is32) {
            int4 a = *(const int4*)&v[E + base];
            d0 = a.x; d1 = a.y; d2 = a.z; d3 = a.w;
        } else {
            int4 a = *(const int4*)&v[2 * E + 2 * base];
            int4 b = *(const int4*)&v[2 * E + 2 * base + 4];
            d0 = a.x; d1 = a.z; d2 = b.x; d3 = b.z;
        }
        if (d0 < (unsigned)N) atomicAdd(&g_cnt[d0], 1);
        if (d1 < (unsigned)N) atomicAdd(&g_cnt[d1], 1);
        if (d2 < (unsigned)N) atomicAdd(&g_cnt[d2], 1);
        if (d3 < (unsigned)N) atomicAdd(&g_cnt[d3], 1);
    } else {
        int s = is32 ? 1 : 2, dbase = is32 ? E : 2 * E;
        for (int i = base; i < E; i++) {
            unsigned d = (unsigned)v[dbase + s * i];
            if (d < (unsigned)N) atomicAdd(&g_cnt[d], 1);
        }
    }
}

// Scan phase 1: 1024 threads (4 blocks) compute partial sums of g_cnt chunks.
__global__ void k_part(int N)
{
    int t = blockIdx.x * blockDim.x + threadIdx.x;
    if (t >= NPART) return;
    int ch  = (N + NPART - 1) / NPART;
    int beg = t * ch;
    int end = min(beg + ch, N);
    int s = 0;
    for (int i = beg; i < end; i++) s += g_cnt[i];
    g_part[t] = s;
}

// Scan phase 2: one warp exclusive-scans the 1024 partials (shfl only).
__global__ void k_scanpart()
{
    int lane = threadIdx.x & 31;                      // <<<1,32>>>
    const int CH = NPART / 32;
    int base = lane * CH;
    int s = 0;
    for (int i = 0; i < CH; i++) s += g_part[base + i];
    int pre = s;
#pragma unroll
    for (int o = 1; o < 32; o <<= 1) {
        int vv = __shfl_up_sync(0xffffffffu, pre, o);
        if (lane >= o) pre += vv;
    }
    int run = pre - s;                                // exclusive base
    for (int i = 0; i < CH; i++) {
        int c = g_part[base + i];
        g_part[base + i] = run;
        run += c;
    }
}

// Scan phase 3: expand partial prefixes into offsets, cursors, dinv.
__global__ void k_offsets(int N, int E)
{
    int t = blockIdx.x * blockDim.x + threadIdx.x;
    if (t >= NPART) return;
    int ch  = (N + NPART - 1) / NPART;
    int beg = t * ch;
    int end = min(beg + ch, N);
    int run = g_part[t];
    for (int i = beg; i < end; i++) {
        int c = g_cnt[i];
        g_off[i]    = run;
        g_cursor[i] = run;
        g_dinv[i]   = rsqrtf((float)(c + 1));         // +1 self loop
        run += c;
    }
    if (t == 0) g_off[N] = E;
}

__global__ void k_fill(const int* __restrict__ v, int E, int N)
{
    int base = (blockIdx.x * blockDim.x + threadIdx.x) * 4;
    if (base >= E) return;
    int is32 = g_odd_or;
    if (base + 4 <= E) {
        unsigned s0, s1, s2, s3, d0, d1, d2, d3;
        if (is32) {
            int4 a = *(const int4*)&v[base];
            int4 b = *(const int4*)&v[E + base];
            s0 = a.x; s1 = a.y; s2 = a.z; s3 = a.w;
            d0 = b.x; d1 = b.y; d2 = b.z; d3 = b.w;
        } else {
            int4 a = *(const int4*)&v[2 * base];
            int4 b = *(const int4*)&v[2 * base + 4];
            int4 c = *(const int4*)&v[2 * E + 2 * base];
            int4 d = *(const int4*)&v[2 * E + 2 * base + 4];
            s0 = a.x; s1 = a.z; s2 = b.x; s3 = b.z;
            d0 = c.x; d1 = c.z; d2 = d.x; d3 = d.z;
        }
        if (d0 < (unsigned)N && s0 < (unsigned)N)
            g_csr_src[atomicAdd(&g_cursor[d0], 1)] = (int)s0;
        if (d1 < (unsigned)N && s1 < (unsigned)N)
            g_csr_src[atomicAdd(&g_cursor[d1], 1)] = (int)s1;
        if (d2 < (unsigned)N && s2 < (unsigned)N)
            g_csr_src[atomicAdd(&g_cursor[d2], 1)] = (int)s2;
        if (d3 < (unsigned)N && s3 < (unsigned)N)
            g_csr_src[atomicAdd(&g_cursor[d3], 1)] = (int)s3;
    } else {
        int s = is32 ? 1 : 2, dbase = is32 ? E : 2 * E;
        for (int i = base; i < E; i++) {
            unsigned d  = (unsigned)v[dbase + s * i];
            unsigned sr = (unsigned)v[s * i];
            if (d < (unsigned)N && sr < (unsigned)N)
                g_csr_src[atomicAdd(&g_cursor[d], 1)] = (int)sr;
        }
    }
}

// ---------------------------------------------------------------------------
// GEMM (FFMA2, K-parity pairing): H16[row] = fp16(X[row] @ W)   (NO dinv)
//   Block 256 thr = 8 warps. Warp tile 32x32, thread tile 8 rows x 4 cols.
// ---------------------------------------------------------------------------
template <int DOUT, int LAYER>
__global__ void __launch_bounds__(256)
k_gemm(const float* __restrict__ Xp, const float* __restrict__ W, int N)
{
    constexpr int KC  = 32;            // K chunk
    constexpr int NK2 = KC / 2;        // 16 k-pairs per chunk
    constexpr int WC  = DOUT / 32;     // warp-cols (4 or 2)
    constexpr int WR  = 8 / WC;        // warp-rows (2 or 4)
    constexpr int BM  = WR * 32;       // block rows (64 or 128)
    constexpr int SX  = BM + (BM >> 4) * 2 + 2;    // swizzled slab strides
    constexpr int SW  = DOUT + (DOUT >> 4) * 2 + 2;

    const float* X = (LAYER == 0) ? Xp : g_x2;
    __half*      H = (LAYER == 0) ? g_hs : g_hs2;

    __shared__ unsigned long long xs2[NK2 * SX];
    __shared__ unsigned long long ws2[NK2 * SW];

    int t    = threadIdx.x;
    int w    = t >> 5;
    int lane = t & 31;
    int rg   = lane >> 3;              // 0..3
    int cg   = lane & 7;               // 0..7
    int warpRow = w / WC;
    int warpCol = w % WC;
    int rowL0   = warpRow * 32 + rg * 8;           // local row base (8 rows)
    int colBase = warpCol * 32 + cg * 4;           // local col base (4 cols)
    int row0    = blockIdx.x * BM;

    unsigned long long acc[8][4];
#pragma unroll
    for (int i = 0; i < 8; i++)
#pragma unroll
        for (int j = 0; j < 4; j++) acc[i][j] = 0ull;

    for (int kk = 0; kk < 128; kk += KC) {
        // ---- stage X chunk: xs2[k2][swz(rowLocal)] = (x_eventk, x_oddk)
#pragma unroll
        for (int u = 0; u < BM / 32; u++) {
            int idx = u * 256 + t;                  // BM*8 units
            int r   = idx >> 3;
            int j4  = idx & 7;                      // float4 index in chunk
            int row = row0 + r;
            float4 x = make_float4(0.f, 0.f, 0.f, 0.f);
            if (row < N) x = *(const float4*)&X[row * 128 + kk + j4 * 4];
            xs2[(2 * j4)     * SX + swz(r)] = pack2(x.x, x.y);
            xs2[(2 * j4 + 1) * SX + swz(r)] = pack2(x.z, x.w);
        }
        // ---- stage W chunk: ws2[k2][swz(col)] = (W[2k2][c], W[2k2+1][c])
#pragma unroll
        for (int u = 0; u < DOUT / 64; u++) {
            int idx = u * 256 + t;                  // 4*DOUT units
            int k2  = idx / (DOUT / 4);
            int c4  = idx % (DOUT / 4);
            const float* wp = &W[(kk + 2 * k2) * DOUT + c4 * 4];
            float4 a = *(const float4*)wp;
            float4 b = *(const float4*)(wp + DOUT);
            int p = k2 * SW + swz(c4 * 4);
            ulonglong2 p0; p0.x = pack2(a.x, b.x); p0.y = pack2(a.y, b.y);
            ulonglong2 p1; p1.x = pack2(a.z, b.z); p1.y = pack2(a.w, b.w);
            *(ulonglong2*)&ws2[p]     = p0;
            *(ulonglong2*)&ws2[p + 2] = p1;
        }
        __syncthreads();

#pragma unroll
        for (int k2 = 0; k2 < NK2; k2++) {
            ulonglong2 xv[4];
#pragma unroll
            for (int j = 0; j < 4; j++)
                xv[j] = *(const ulonglong2*)&xs2[k2 * SX + swz(rowL0 + 2 * j)];
            ulonglong2 wv0 = *(const ulonglong2*)&ws2[k2 * SW + swz(colBase)];
            ulonglong2 wv1 = *(const ulonglong2*)&ws2[k2 * SW + swz(colBase + 2)];
#pragma unroll
            for (int j = 0; j < 4; j++) {
                ffma2(acc[2 * j][0],     xv[j].x, wv0.x);
                ffma2(acc[2 * j][1],     xv[j].x, wv0.y);
                ffma2(acc[2 * j][2],     xv[j].x, wv1.x);
                ffma2(acc[2 * j][3],     xv[j].x, wv1.y);
                ffma2(acc[2 * j + 1][0], xv[j].y, wv0.x);
                ffma2(acc[2 * j + 1][1], xv[j].y, wv0.y);
                ffma2(acc[2 * j + 1][2], xv[j].y, wv1.x);
                ffma2(acc[2 * j + 1][3], xv[j].y, wv1.y);
            }
        }
        __syncthreads();
    }

    // epilogue: fold k-parity pairs, convert fp16, store
#pragma unroll
    for (int i = 0; i < 8; i++) {
        int row = row0 + rowL0 + i;
        if (row < N) {
            float f[4];
#pragma unroll
            for (int j = 0; j < 4; j++) {
                float lo, hi;
                unpack2(acc[i][j], lo, hi);
                f[j] = lo + hi;
            }
            __half2 h01 = __floats2half2_rn(f[0], f[1]);
            __half2 h23 = __floats2half2_rn(f[2], f[3]);
            uint2 o;
            o.x = *(unsigned*)&h01;
            o.y = *(unsigned*)&h23;
            *(uint2*)&H[row * DOUT + colBase] = o;
        }
    }
}

// ---------------------------------------------------------------------------
// Aggregate per dst node:
//   OUT[d] = dinv[d]*( HS[d]*dinv[d] + sum_in HS[src]*dinv[src] ) + b (+relu)
//   HS is fp16 (halved gather traffic); accumulation fp32; 4-way edge unroll.
// ---------------------------------------------------------------------------
template <int DOUT, bool RELU, int LAYER>
__global__ void k_agg(const float* __restrict__ bias,
                      float* __restrict__ outp, int N)
{
    constexpr int TPN = DOUT / 8;         // threads per node
    constexpr int NPB = 256 / TPN;        // nodes per block

    const __half* HS  = (LAYER == 0) ? g_hs : g_hs2;
    float*        OUT = (LAYER == 0) ? g_x2 : outp;

    int t    = threadIdx.x;
    int node = blockIdx.x * NPB + t / TPN;
    int c8   = (t % TPN) * 8;
    if (node >= N) return;

    float dnode = g_dinv[node];
    float a[8];
    {   // self loop: HS[d]*dinv[d]
        uint4 v = *(const uint4*)&HS[node * DOUT + c8];
        float2 f0 = __half22float2(*(__half2*)&v.x);
        float2 f1 = __half22float2(*(__half2*)&v.y);
        float2 f2 = __half22float2(*(__half2*)&v.z);
        float2 f3 = __half22float2(*(__half2*)&v.w);
        a[0] = f0.x * dnode; a[1] = f0.y * dnode;
        a[2] = f1.x * dnode; a[3] = f1.y * dnode;
        a[4] = f2.x * dnode; a[5] = f2.y * dnode;
        a[6] = f3.x * dnode; a[7] = f3.y * dnode;
    }

    int i = g_off[node];
    int e = g_off[node + 1];
    for (; i + 4 <= e; i += 4) {
        int s0 = g_csr_src[i + 0];
        int s1 = g_csr_src[i + 1];
        int s2 = g_csr_src[i + 2];
        int s3 = g_csr_src[i + 3];
        uint4 v0 = *(const uint4*)&HS[s0 * DOUT + c8];
        uint4 v1 = *(const uint4*)&HS[s1 * DOUT + c8];
        uint4 v2 = *(const uint4*)&HS[s2 * DOUT + c8];
        uint4 v3 = *(const uint4*)&HS[s3 * DOUT + c8];
        float dv0 = g_dinv[s0];
        float dv1 = g_dinv[s1];
        float dv2 = g_dinv[s2];
        float dv3 = g_dinv[s3];
#pragma unroll
        for (int q = 0; q < 4; q++) {
            unsigned w0 = (&v0.x)[q], w1 = (&v1.x)[q],
                     w2 = (&v2.x)[q], w3 = (&v3.x)[q];
            float2 f0 = __half22float2(*(__half2*)&w0);
            float2 f1 = __half22float2(*(__half2*)&w1);
            float2 f2 = __half22float2(*(__half2*)&w2);
            float2 f3 = __half22float2(*(__half2*)&w3);
            a[2 * q]     = fmaf(f0.x, dv0, a[2 * q]);
            a[2 * q]     = fmaf(f1.x, dv1, a[2 * q]);
            a[2 * q]     = fmaf(f2.x, dv2, a[2 * q]);
            a[2 * q]     = fmaf(f3.x, dv3, a[2 * q]);
            a[2 * q + 1] = fmaf(f0.y, dv0, a[2 * q + 1]);
            a[2 * q + 1] = fmaf(f1.y, dv1, a[2 * q + 1]);
            a[2 * q + 1] = fmaf(f2.y, dv2, a[2 * q + 1]);
            a[2 * q + 1] = fmaf(f3.y, dv3, a[2 * q + 1]);
        }
    }
    for (; i < e; i++) {
        int s0 = g_csr_src[i];
        uint4 v = *(const uint4*)&HS[s0 * DOUT + c8];
        float dv = g_dinv[s0];
#pragma unroll
        for (int q = 0; q < 4; q++) {
            unsigned w0 = (&v.x)[q];
            float2 f = __half22float2(*(__half2*)&w0);
            a[2 * q]     = fmaf(f.x, dv, a[2 * q]);
            a[2 * q + 1] = fmaf(f.y, dv, a[2 * q + 1]);
        }
    }

    float r[8];
#pragma unroll
    for (int q = 0; q < 8; q++) {
        float o = a[q] * dnode + bias[c8 + q];
        if (RELU) o = fmaxf(o, 0.f);
        r[q] = o;
    }
    float4 ob0 = make_float4(r[0], r[1], r[2], r[3]);
    float4 ob1 = make_float4(r[4], r[5], r[6], r[7]);
    *(float4*)&OUT[node * DOUT + c8]     = ob0;
    *(float4*)&OUT[node * DOUT + c8 + 4] = ob1;
}

// ---------------------------------------------------------------------------
extern "C" void kernel_launch(void* const* d_in, const int* in_sizes, int n_in,
                              void* d_out, int out_size)
{
    const float* e_prev = (const float*)d_in[0];
    const int*   ei     = (const int*)d_in[1];   // int32 view; dtype detected
    const float* W1     = (const float*)d_in[2];
    const float* b1     = (const float*)d_in[3];
    const float* W2     = (const float*)d_in[4];
    const float* b2     = (const float*)d_in[5];
    float*       out    = (float*)d_out;

    int N = in_sizes[0] / 128;   // 50000
    int E = in_sizes[1] / 2;     // 800000 (element count, dtype-independent)

    cudaStream_t s0 = 0;
    bool forked = g_ss.ok;
    cudaStream_t sg = forked ? g_ss.s2 : s0;   // stream for gemm1 branch

    if (forked) {
        cudaEventRecord(g_ss.fork, s0);
        cudaStreamWaitEvent(sg, g_ss.fork, 0);
    }

    // Branch B: layer-1 GEMM (independent of CSR build)
    k_gemm<128, 0><<<(N + 63) / 64, 256, 0, sg>>>(e_prev, W1, N);
    if (forked) {
        cudaEventRecord(g_ss.joinB, sg);
    }

    // Branch A: CSR build (hierarchical scan, all phases parallel)
    k_init<<<(N + 255) / 256, 256, 0, s0>>>(ei, N);
    k_hist<<<(E / 4 + 255) / 256, 256, 0, s0>>>(ei, E, N);
    k_part<<<NPART / 256, 256, 0, s0>>>(N);
    k_scanpart<<<1, 32, 0, s0>>>();
    k_offsets<<<NPART / 256, 256, 0, s0>>>(N, E);
    k_fill<<<(E / 4 + 255) / 256, 256, 0, s0>>>(ei, E, N);

    if (forked) {
        cudaStreamWaitEvent(s0, g_ss.joinB, 0);
    }

    // Join: aggregation + layer 2 (sequential on s0)
    {
        constexpr int NPB = 256 / (128 / 8);      // 16 nodes per block
        k_agg<128, true, 0><<<(N + NPB - 1) / NPB, 256, 0, s0>>>(b1, nullptr, N);
    }
    k_gemm<64, 1><<<(N + 127) / 128, 256, 0, s0>>>(nullptr, W2, N);
    {
        constexpr int NPB = 256 / (64 / 8);       // 32 nodes per block
        k_agg<64, false, 1><<<(N + NPB - 1) / NPB, 256, 0, s0>>>(b2, out, N);
    }
}

// round 9
// speedup vs baseline: 1.3608x; 1.3608x over previous
#include <cuda_runtime.h>
#include <cuda_fp16.h>

// ---------------------------------------------------------------------------
// GNNEncoder: 2-layer GCN. out[d] = dinv[d]*sum_{(s,d)}(x[s]@W)*dinv[s] + b
// R9: fully sequential 8-kernel pipeline for timeline decomposability:
//   [init, hist, scan1(single-block coalesced block-scan), fill,
//    gemm1, agg1, gemm2, agg2]   -> ncu -s5 captures agg1 (launch #6).
//   - fork/join removed (measured no benefit)
//   - dinv folded back into GEMM epilogue (agg loses per-edge dinv gathers)
//   - FFMA2 register-tiled GEMM; fp16 gather storage, fp32 accumulation
// All scratch in __device__ globals; graph-capturable (kernel launches only).
// ---------------------------------------------------------------------------

#define NODES_MAX 50000
#define EDGES_MAX 800000

__device__ int    g_odd_or;                 // !=0 => edge_index is int32
__device__ int    g_cnt[NODES_MAX];
__device__ int    g_off[NODES_MAX + 1];
__device__ int    g_cursor[NODES_MAX];
__device__ int    g_csr_src[EDGES_MAX];
__device__ float  g_dinv[NODES_MAX];
__device__ __half g_hs [NODES_MAX * 128];   // layer1 (x@W1)*dinv   (gathered)
__device__ float  g_x2 [NODES_MAX * 128];   // layer1 output (post relu)
__device__ __half g_hs2[NODES_MAX * 64];    // layer2 (x2@W2)*dinv  (gathered)

// ---- f32x2 helpers --------------------------------------------------------
__device__ __forceinline__ unsigned long long pack2(float lo, float hi)
{
    unsigned long long r;
    asm("mov.b64 %0, {%1, %2};" : "=l"(r) : "f"(lo), "f"(hi));
    return r;
}
__device__ __forceinline__ void unpack2(unsigned long long v, float& lo, float& hi)
{
    asm("mov.b64 {%0, %1}, %2;" : "=f"(lo), "=f"(hi) : "l"(v));
}
__device__ __forceinline__ void ffma2(unsigned long long& d,
                                      unsigned long long a,
                                      unsigned long long b)
{
    asm("fma.rn.f32x2 %0, %1, %2, %3;" : "=l"(d) : "l"(a), "l"(b), "l"(d));
}

// smem anti-conflict swizzle: insert a 2-entry (16B) gap every 16 entries.
__device__ __forceinline__ int swz(int i) { return i + ((i >> 4) << 1); }

// ---- CSR build --------------------------------------------------------------
__global__ void k_init(const int* __restrict__ v, int N)
{
    int i = blockIdx.x * blockDim.x + threadIdx.x;
    if (i < N) g_cnt[i] = 0;
    if (i == 0) g_odd_or = 0;
    // dtype detect: int64 viewed as int32 pairs -> odd words all zero.
    if (i < 256 && v[2 * i + 1] != 0) atomicOr(&g_odd_or, 1);
}

__global__ void k_hist(const int* __restrict__ v, int E, int N)
{
    int base = (blockIdx.x * blockDim.x + threadIdx.x) * 4;
    if (base >= E) return;
    int is32 = g_odd_or;
    if (base + 4 <= E) {
        unsigned d0, d1, d2, d3;
        if (is32) {
            int4 a = *(const int4*)&v[E + base];
            d0 = a.x; d1 = a.y; d2 = a.z; d3 = a.w;
        } else {
            int4 a = *(const int4*)&v[2 * E + 2 * base];
            int4 b = *(const int4*)&v[2 * E + 2 * base + 4];
            d0 = a.x; d1 = a.z; d2 = b.x; d3 = b.z;
        }
        if (d0 < (unsigned)N) atomicAdd(&g_cnt[d0], 1);
        if (d1 < (unsigned)N) atomicAdd(&g_cnt[d1], 1);
        if (d2 < (unsigned)N) atomicAdd(&g_cnt[d2], 1);
        if (d3 < (unsigned)N) atomicAdd(&g_cnt[d3], 1);
    } else {
        int s = is32 ? 1 : 2, dbase = is32 ? E : 2 * E;
        for (int i = base; i < E; i++) {
            unsigned d = (unsigned)v[dbase + s * i];
            if (d < (unsigned)N) atomicAdd(&g_cnt[d], 1);
        }
    }
}

// Single-block COALESCED block-scan: tiles of 1024, shfl warp scan + smem
// inter-warp scan, running carry. All loads/stores coalesced (unlike the
// 103us per-thread-chunk version).
__global__ void __launch_bounds__(1024) k_scan1(int N, int E)
{
    __shared__ int wsum[32];
    __shared__ int stot;
    int t    = threadIdx.x;
    int lane = t & 31;
    int wid  = t >> 5;
    int carry = 0;
    int ntiles = (N + 1023) >> 10;

    for (int tile = 0; tile < ntiles; tile++) {
        int i = (tile << 10) + t;
        int c = (i < N) ? g_cnt[i] : 0;

        // warp-inclusive scan of c
        int incl = c;
#pragma unroll
        for (int o = 1; o < 32; o <<= 1) {
            int vv = __shfl_up_sync(0xffffffffu, incl, o);
            if (lane >= o) incl += vv;
        }
        if (lane == 31) wsum[wid] = incl;
        __syncthreads();

        if (wid == 0) {
            int s  = wsum[lane];
            int si = s;
#pragma unroll
            for (int o = 1; o < 32; o <<= 1) {
                int vv = __shfl_up_sync(0xffffffffu, si, o);
                if (lane >= o) si += vv;
            }
            wsum[lane] = si - s;            // exclusive inter-warp prefix
            if (lane == 31) stot = si;      // tile total
        }
        __syncthreads();

        int off = carry + wsum[wid] + incl - c;   // exclusive global prefix
        if (i < N) {
            g_off[i]    = off;
            g_cursor[i] = off;
            g_dinv[i]   = rsqrtf((float)(c + 1));  // +1 self loop
        }
        carry += stot;
        __syncthreads();                    // protect wsum/stot for next tile
    }
    if (t == 0) g_off[N] = E;
}

__global__ void k_fill(const int* __restrict__ v, int E, int N)
{
    int base = (blockIdx.x * blockDim.x + threadIdx.x) * 4;
    if (base >= E) return;
    int is32 = g_odd_or;
    if (base + 4 <= E) {
        unsigned s0, s1, s2, s3, d0, d1, d2, d3;
        if (is32) {
            int4 a = *(const int4*)&v[base];
            int4 b = *(const int4*)&v[E + base];
            s0 = a.x; s1 = a.y; s2 = a.z; s3 = a.w;
            d0 = b.x; d1 = b.y; d2 = b.z; d3 = b.w;
        } else {
            int4 a = *(const int4*)&v[2 * base];
            int4 b = *(const int4*)&v[2 * base + 4];
            int4 c = *(const int4*)&v[2 * E + 2 * base];
            int4 d = *(const int4*)&v[2 * E + 2 * base + 4];
            s0 = a.x; s1 = a.z; s2 = b.x; s3 = b.z;
            d0 = c.x; d1 = c.z; d2 = d.x; d3 = d.z;
        }
        if (d0 < (unsigned)N && s0 < (unsigned)N)
            g_csr_src[atomicAdd(&g_cursor[d0], 1)] = (int)s0;
        if (d1 < (unsigned)N && s1 < (unsigned)N)
            g_csr_src[atomicAdd(&g_cursor[d1], 1)] = (int)s1;
        if (d2 < (unsigned)N && s2 < (unsigned)N)
            g_csr_src[atomicAdd(&g_cursor[d2], 1)] = (int)s2;
        if (d3 < (unsigned)N && s3 < (unsigned)N)
            g_csr_src[atomicAdd(&g_cursor[d3], 1)] = (int)s3;
    } else {
        int s = is32 ? 1 : 2, dbase = is32 ? E : 2 * E;
        for (int i = base; i < E; i++) {
            unsigned d  = (unsigned)v[dbase + s * i];
            unsigned sr = (unsigned)v[s * i];
            if (d < (unsigned)N && sr < (unsigned)N)
                g_csr_src[atomicAdd(&g_cursor[d], 1)] = (int)sr;
        }
    }
}

// ---------------------------------------------------------------------------
// GEMM (FFMA2, K-parity pairing): H16[row] = fp16((X[row] @ W) * dinv[row])
//   Block 256 thr = 8 warps. Warp tile 32x32, thread tile 8 rows x 4 cols.
// ---------------------------------------------------------------------------
template <int DOUT, int LAYER>
__global__ void __launch_bounds__(256)
k_gemm(const float* __restrict__ Xp, const float* __restrict__ W, int N)
{
    constexpr int KC  = 32;            // K chunk
    constexpr int NK2 = KC / 2;        // 16 k-pairs per chunk
    constexpr int WC  = DOUT / 32;     // warp-cols (4 or 2)
    constexpr int WR  = 8 / WC;        // warp-rows (2 or 4)
    constexpr int BM  = WR * 32;       // block rows (64 or 128)
    constexpr int SX  = BM + (BM >> 4) * 2 + 2;    // swizzled slab strides
    constexpr int SW  = DOUT + (DOUT >> 4) * 2 + 2;

    const float* X = (LAYER == 0) ? Xp : g_x2;
    __half*      H = (LAYER == 0) ? g_hs : g_hs2;

    __shared__ unsigned long long xs2[NK2 * SX];
    __shared__ unsigned long long ws2[NK2 * SW];

    int t    = threadIdx.x;
    int w    = t >> 5;
    int lane = t & 31;
    int rg   = lane >> 3;              // 0..3
    int cg   = lane & 7;               // 0..7
    int warpRow = w / WC;
    int warpCol = w % WC;
    int rowL0   = warpRow * 32 + rg * 8;           // local row base (8 rows)
    int colBase = warpCol * 32 + cg * 4;           // local col base (4 cols)
    int row0    = blockIdx.x * BM;

    unsigned long long acc[8][4];
#pragma unroll
    for (int i = 0; i < 8; i++)
#pragma unroll
        for (int j = 0; j < 4; j++) acc[i][j] = 0ull;

    for (int kk = 0; kk < 128; kk += KC) {
        // ---- stage X chunk: xs2[k2][swz(rowLocal)] = (x_eventk, x_oddk)
#pragma unroll
        for (int u = 0; u < BM / 32; u++) {
            int idx = u * 256 + t;                  // BM*8 units
            int r   = idx >> 3;
            int j4  = idx & 7;                      // float4 index in chunk
            int row = row0 + r;
            float4 x = make_float4(0.f, 0.f, 0.f, 0.f);
            if (row < N) x = *(const float4*)&X[row * 128 + kk + j4 * 4];
            xs2[(2 * j4)     * SX + swz(r)] = pack2(x.x, x.y);
            xs2[(2 * j4 + 1) * SX + swz(r)] = pack2(x.z, x.w);
        }
        // ---- stage W chunk: ws2[k2][swz(col)] = (W[2k2][c], W[2k2+1][c])
#pragma unroll
        for (int u = 0; u < DOUT / 64; u++) {
            int idx = u * 256 + t;                  // 4*DOUT units
            int k2  = idx / (DOUT / 4);
            int c4  = idx % (DOUT / 4);
            const float* wp = &W[(kk + 2 * k2) * DOUT + c4 * 4];
            float4 a = *(const float4*)wp;
            float4 b = *(const float4*)(wp + DOUT);
            int p = k2 * SW + swz(c4 * 4);
            ulonglong2 p0; p0.x = pack2(a.x, b.x); p0.y = pack2(a.y, b.y);
            ulonglong2 p1; p1.x = pack2(a.z, b.z); p1.y = pack2(a.w, b.w);
            *(ulonglong2*)&ws2[p]     = p0;
            *(ulonglong2*)&ws2[p + 2] = p1;
        }
        __syncthreads();

#pragma unroll
        for (int k2 = 0; k2 < NK2; k2++) {
            ulonglong2 xv[4];
#pragma unroll
            for (int j = 0; j < 4; j++)
                xv[j] = *(const ulonglong2*)&xs2[k2 * SX + swz(rowL0 + 2 * j)];
            ulonglong2 wv0 = *(const ulonglong2*)&ws2[k2 * SW + swz(colBase)];
            ulonglong2 wv1 = *(const ulonglong2*)&ws2[k2 * SW + swz(colBase + 2)];
#pragma unroll
            for (int j = 0; j < 4; j++) {
                ffma2(acc[2 * j][0],     xv[j].x, wv0.x);
                ffma2(acc[2 * j][1],     xv[j].x, wv0.y);
                ffma2(acc[2 * j][2],     xv[j].x, wv1.x);
                ffma2(acc[2 * j][3],     xv[j].x, wv1.y);
                ffma2(acc[2 * j + 1][0], xv[j].y, wv0.x);
                ffma2(acc[2 * j + 1][1], xv[j].y, wv0.y);
                ffma2(acc[2 * j + 1][2], xv[j].y, wv1.x);
                ffma2(acc[2 * j + 1][3], xv[j].y, wv1.y);
            }
        }
        __syncthreads();
    }

    // epilogue: fold k-parity pairs, scale by dinv, convert fp16, store
#pragma unroll
    for (int i = 0; i < 8; i++) {
        int row = row0 + rowL0 + i;
        if (row < N) {
            float s = g_dinv[row];
            float f[4];
#pragma unroll
            for (int j = 0; j < 4; j++) {
                float lo, hi;
                unpack2(acc[i][j], lo, hi);
                f[j] = (lo + hi) * s;
            }
            __half2 h01 = __floats2half2_rn(f[0], f[1]);
            __half2 h23 = __floats2half2_rn(f[2], f[3]);
            uint2 o;
            o.x = *(unsigned*)&h01;
            o.y = *(unsigned*)&h23;
            *(uint2*)&H[row * DOUT + colBase] = o;
        }
    }
}

// ---------------------------------------------------------------------------
// Aggregate per dst node: OUT[d] = dinv[d]*(HS[d] + sum_in HS[src]) + b (+relu)
//   HS is fp16; accumulation fp32; 4-way edge unroll for MLP.
// ---------------------------------------------------------------------------
template <int DOUT, bool RELU, int LAYER>
__global__ void k_agg(const float* __restrict__ bias,
                      float* __restrict__ outp, int N)
{
    constexpr int TPN = DOUT / 8;         // threads per node
    constexpr int NPB = 256 / TPN;        // nodes per block

    const __half* HS  = (LAYER == 0) ? g_hs : g_hs2;
    float*        OUT = (LAYER == 0) ? g_x2 : outp;

    int t    = threadIdx.x;
    int node = blockIdx.x * NPB + t / TPN;
    int c8   = (t % TPN) * 8;
    if (node >= N) return;

    float a[8];
    {   // self loop
        uint4 v = *(const uint4*)&HS[node * DOUT + c8];
        float2 f0 = __half22float2(*(__half2*)&v.x);
        float2 f1 = __half22float2(*(__half2*)&v.y);
        float2 f2 = __half22float2(*(__half2*)&v.z);
        float2 f3 = __half22float2(*(__half2*)&v.w);
        a[0] = f0.x; a[1] = f0.y; a[2] = f1.x; a[3] = f1.y;
        a[4] = f2.x; a[5] = f2.y; a[6] = f3.x; a[7] = f3.y;
    }

    int i = g_off[node];
    int e = g_off[node + 1];
    for (; i + 4 <= e; i += 4) {
        int s0 = g_csr_src[i + 0];
        int s1 = g_csr_src[i + 1];
        int s2 = g_csr_src[i + 2];
        int s3 = g_csr_src[i + 3];
        uint4 v0 = *(const uint4*)&HS[s0 * DOUT + c8];
        uint4 v1 = *(const uint4*)&HS[s1 * DOUT + c8];
        uint4 v2 = *(const uint4*)&HS[s2 * DOUT + c8];
        uint4 v3 = *(const uint4*)&HS[s3 * DOUT + c8];
#pragma unroll
        for (int q = 0; q < 4; q++) {
            unsigned w0 = (&v0.x)[q], w1 = (&v1.x)[q],
                     w2 = (&v2.x)[q], w3 = (&v3.x)[q];
            float2 f0 = __half22float2(*(__half2*)&w0);
            float2 f1 = __half22float2(*(__half2*)&w1);
            float2 f2 = __half22float2(*(__half2*)&w2);
            float2 f3 = __half22float2(*(__half2*)&w3);
            a[2 * q]     += f0.x + f1.x + f2.x + f3.x;
            a[2 * q + 1] += f0.y + f1.y + f2.y + f3.y;
        }
    }
    for (; i < e; i++) {
        int s0 = g_csr_src[i];
        uint4 v = *(const uint4*)&HS[s0 * DOUT + c8];
#pragma unroll
        for (int q = 0; q < 4; q++) {
            unsigned w0 = (&v.x)[q];
            float2 f = __half22float2(*(__half2*)&w0);
            a[2 * q]     += f.x;
            a[2 * q + 1] += f.y;
        }
    }

    float d = g_dinv[node];
    float r[8];
#pragma unroll
    for (int q = 0; q < 8; q++) {
        float o = a[q] * d + bias[c8 + q];
        if (RELU) o = fmaxf(o, 0.f);
        r[q] = o;
    }
    float4 ob0 = make_float4(r[0], r[1], r[2], r[3]);
    float4 ob1 = make_float4(r[4], r[5], r[6], r[7]);
    *(float4*)&OUT[node * DOUT + c8]     = ob0;
    *(float4*)&OUT[node * DOUT + c8 + 4] = ob1;
}

// ---------------------------------------------------------------------------
extern "C" void kernel_launch(void* const* d_in, const int* in_sizes, int n_in,
                              void* d_out, int out_size)
{
    const float* e_prev = (const float*)d_in[0];
    const int*   ei     = (const int*)d_in[1];   // int32 view; dtype detected
    const float* W1     = (const float*)d_in[2];
    const float* b1     = (const float*)d_in[3];
    const float* W2     = (const float*)d_in[4];
    const float* b2     = (const float*)d_in[5];
    float*       out    = (float*)d_out;

    int N = in_sizes[0] / 128;   // 50000
    int E = in_sizes[1] / 2;     // 800000 (element count, dtype-independent)

    // CSR build (sequential, decomposable)
    k_init <<<(N + 255) / 256, 256>>>(ei, N);            // #1
    k_hist <<<(E / 4 + 255) / 256, 256>>>(ei, E, N);     // #2
    k_scan1<<<1, 1024>>>(N, E);                          // #3
    k_fill <<<(E / 4 + 255) / 256, 256>>>(ei, E, N);     // #4

    // Layer 1
    k_gemm<128, 0><<<(N + 63) / 64, 256>>>(e_prev, W1, N);        // #5
    {
        constexpr int NPB = 256 / (128 / 8);      // 16 nodes per block
        k_agg<128, true, 0><<<(N + NPB - 1) / NPB, 256>>>(b1, nullptr, N); // #6
    }

    // Layer 2
    k_gemm<64, 1><<<(N + 127) / 128, 256>>>(nullptr, W2, N);      // #7
    {
        constexpr int NPB = 256 / (64 / 8);       // 32 nodes per block
        k_agg<64, false, 1><<<(N + NPB - 1) / NPB, 256>>>(b2, out, N); // #8
    }
}

// round 10
// speedup vs baseline: 1.6585x; 1.2188x over previous
#include <cuda_runtime.h>
#include <cuda_fp16.h>

// ---------------------------------------------------------------------------
// GNNEncoder: 2-layer GCN. out[d] = dinv[d]*sum_{(s,d)}(x[s]@W)*dinv[s] + b
// R10: tensor-core GEMM via mma.sync.m16n8k16 (f16 in, f32 accumulate) with
//      2-term input split (X=Xh+Xl, W=Wh+Wl; 3 mma/tile) -> fp32-grade
//      accuracy at HMMA speed. Sequential 8-kernel pipeline (forks measured
//      harmful). CSR build + fp16-gather aggregation unchanged from R9.
// All scratch in __device__ globals; graph-capturable (kernel launches only).
// ---------------------------------------------------------------------------

#define NODES_MAX 50000
#define EDGES_MAX 800000

__device__ int    g_odd_or;                 // !=0 => edge_index is int32
__device__ int    g_cnt[NODES_MAX];
__device__ int    g_off[NODES_MAX + 1];
__device__ int    g_cursor[NODES_MAX];
__device__ int    g_csr_src[EDGES_MAX];
__device__ float  g_dinv[NODES_MAX];
__device__ __half g_hs [NODES_MAX * 128];   // layer1 (x@W1)*dinv   (gathered)
__device__ float  g_x2 [NODES_MAX * 128];   // layer1 output (post relu)
__device__ __half g_hs2[NODES_MAX * 64];    // layer2 (x2@W2)*dinv  (gathered)

// ---- helpers ----------------------------------------------------------------
__device__ __forceinline__ unsigned sptr(const void* p)
{
    return (unsigned)__cvta_generic_to_shared(p);
}

__device__ __forceinline__ void ldm_x4(unsigned addr, unsigned& r0, unsigned& r1,
                                       unsigned& r2, unsigned& r3)
{
    asm volatile("ldmatrix.sync.aligned.m8n8.x4.shared.b16 {%0,%1,%2,%3}, [%4];"
                 : "=r"(r0), "=r"(r1), "=r"(r2), "=r"(r3) : "r"(addr));
}

__device__ __forceinline__ void ldm_x4t(unsigned addr, unsigned& r0, unsigned& r1,
                                        unsigned& r2, unsigned& r3)
{
    asm volatile("ldmatrix.sync.aligned.m8n8.x4.trans.shared.b16 {%0,%1,%2,%3}, [%4];"
                 : "=r"(r0), "=r"(r1), "=r"(r2), "=r"(r3) : "r"(addr));
}

__device__ __forceinline__ void mma16816(float* d, const unsigned* a,
                                         unsigned b0, unsigned b1)
{
    asm volatile(
        "mma.sync.aligned.m16n8k16.row.col.f32.f16.f16.f32 "
        "{%0,%1,%2,%3}, {%4,%5,%6,%7}, {%8,%9}, {%0,%1,%2,%3};"
        : "+f"(d[0]), "+f"(d[1]), "+f"(d[2]), "+f"(d[3])
        : "r"(a[0]), "r"(a[1]), "r"(a[2]), "r"(a[3]), "r"(b0), "r"(b1));
}

// split a float4 into hi/lo half2 pairs (x = h + l exactly to ~2^-22)
__device__ __forceinline__ void split4(float4 v, uint2& hi, uint2& lo)
{
    __half hx = __float2half_rn(v.x), hy = __float2half_rn(v.y);
    __half hz = __float2half_rn(v.z), hw = __float2half_rn(v.w);
    __half lx = __float2half_rn(v.x - __half2float(hx));
    __half ly = __float2half_rn(v.y - __half2float(hy));
    __half lz = __float2half_rn(v.z - __half2float(hz));
    __half lw = __float2half_rn(v.w - __half2float(hw));
    __half2 h01 = __halves2half2(hx, hy), h23 = __halves2half2(hz, hw);
    __half2 l01 = __halves2half2(lx, ly), l23 = __halves2half2(lz, lw);
    hi.x = *(unsigned*)&h01; hi.y = *(unsigned*)&h23;
    lo.x = *(unsigned*)&l01; lo.y = *(unsigned*)&l23;
}

// ---- CSR build --------------------------------------------------------------
__global__ void k_init(const int* __restrict__ v, int N)
{
    int i = blockIdx.x * blockDim.x + threadIdx.x;
    if (i < N) g_cnt[i] = 0;
    if (i == 0) g_odd_or = 0;
    if (i < 256 && v[2 * i + 1] != 0) atomicOr(&g_odd_or, 1);
}

__global__ void k_hist(const int* __restrict__ v, int E, int N)
{
    int base = (blockIdx.x * blockDim.x + threadIdx.x) * 4;
    if (base >= E) return;
    int is32 = g_odd_or;
    if (base + 4 <= E) {
        unsigned d0, d1, d2, d3;
        if (is32) {
            int4 a = *(const int4*)&v[E + base];
            d0 = a.x; d1 = a.y; d2 = a.z; d3 = a.w;
        } else {
            int4 a = *(const int4*)&v[2 * E + 2 * base];
            int4 b = *(const int4*)&v[2 * E + 2 * base + 4];
            d0 = a.x; d1 = a.z; d2 = b.x; d3 = b.z;
        }
        if (d0 < (unsigned)N) atomicAdd(&g_cnt[d0], 1);
        if (d1 < (unsigned)N) atomicAdd(&g_cnt[d1], 1);
        if (d2 < (unsigned)N) atomicAdd(&g_cnt[d2], 1);
        if (d3 < (unsigned)N) atomicAdd(&g_cnt[d3], 1);
    } else {
        int s = is32 ? 1 : 2, dbase = is32 ? E : 2 * E;
        for (int i = base; i < E; i++) {
            unsigned d = (unsigned)v[dbase + s * i];
            if (d < (unsigned)N) atomicAdd(&g_cnt[d], 1);
        }
    }
}

// Single-block coalesced block-scan (tiles of 1024, shfl + smem, carry).
__global__ void __launch_bounds__(1024) k_scan1(int N, int E)
{
    __shared__ int wsum[32];
    __shared__ int stot;
    int t    = threadIdx.x;
    int lane = t & 31;
    int wid  = t >> 5;
    int carry = 0;
    int ntiles = (N + 1023) >> 10;

    for (int tile = 0; tile < ntiles; tile++) {
        int i = (tile << 10) + t;
        int c = (i < N) ? g_cnt[i] : 0;
        int incl = c;
#pragma unroll
        for (int o = 1; o < 32; o <<= 1) {
            int vv = __shfl_up_sync(0xffffffffu, incl, o);
            if (lane >= o) incl += vv;
        }
        if (lane == 31) wsum[wid] = incl;
        __syncthreads();
        if (wid == 0) {
            int s  = wsum[lane];
            int si = s;
#pragma unroll
            for (int o = 1; o < 32; o <<= 1) {
                int vv = __shfl_up_sync(0xffffffffu, si, o);
                if (lane >= o) si += vv;
            }
            wsum[lane] = si - s;
            if (lane == 31) stot = si;
        }
        __syncthreads();
        int off = carry + wsum[wid] + incl - c;
        if (i < N) {
            g_off[i]    = off;
            g_cursor[i] = off;
            g_dinv[i]   = rsqrtf((float)(c + 1));
        }
        carry += stot;
        __syncthreads();
    }
    if (t == 0) g_off[N] = E;
}

__global__ void k_fill(const int* __restrict__ v, int E, int N)
{
    int base = (blockIdx.x * blockDim.x + threadIdx.x) * 4;
    if (base >= E) return;
    int is32 = g_odd_or;
    if (base + 4 <= E) {
        unsigned s0, s1, s2, s3, d0, d1, d2, d3;
        if (is32) {
            int4 a = *(const int4*)&v[base];
            int4 b = *(const int4*)&v[E + base];
            s0 = a.x; s1 = a.y; s2 = a.z; s3 = a.w;
            d0 = b.x; d1 = b.y; d2 = b.z; d3 = b.w;
        } else {
            int4 a = *(const int4*)&v[2 * base];
            int4 b = *(const int4*)&v[2 * base + 4];
            int4 c = *(const int4*)&v[2 * E + 2 * base];
            int4 d = *(const int4*)&v[2 * E + 2 * base + 4];
            s0 = a.x; s1 = a.z; s2 = b.x; s3 = b.z;
            d0 = c.x; d1 = c.z; d2 = d.x; d3 = d.z;
        }
        if (d0 < (unsigned)N && s0 < (unsigned)N)
            g_csr_src[atomicAdd(&g_cursor[d0], 1)] = (int)s0;
        if (d1 < (unsigned)N && s1 < (unsigned)N)
            g_csr_src[atomicAdd(&g_cursor[d1], 1)] = (int)s1;
        if (d2 < (unsigned)N && s2 < (unsigned)N)
            g_csr_src[atomicAdd(&g_cursor[d2], 1)] = (int)s2;
        if (d3 < (unsigned)N && s3 < (unsigned)N)
            g_csr_src[atomicAdd(&g_cursor[d3], 1)] = (int)s3;
    } else {
        int s = is32 ? 1 : 2, dbase = is32 ? E : 2 * E;
        for (int i = base; i < E; i++) {
            unsigned d  = (unsigned)v[dbase + s * i];
            unsigned sr = (unsigned)v[s * i];
            if (d < (unsigned)N && sr < (unsigned)N)
                g_csr_src[atomicAdd(&g_cursor[d], 1)] = (int)sr;
        }
    }
}

// ---------------------------------------------------------------------------
// Tensor-core GEMM with 2-term split:
//   H16[row] = fp16(((Xh+Xl)[row] @ (Wh+Wl)) * dinv[row]),
//   D = Xh*Wh + Xh*Wl + Xl*Wh   (f32 accumulate; error ~2^-22)
// Block 256 = 8 warps; warp tile 32x32 (2 m-tiles x 4 n-tiles of 16x8).
// BK=32 k-chunk; ldmatrix with padded strides (conflict-free, checked mod128).
// ---------------------------------------------------------------------------
template <int DOUT, int LAYER>
__global__ void __launch_bounds__(256)
k_gemm(const float* __restrict__ Xp, const float* __restrict__ W, int N)
{
    constexpr int BK  = 32;
    constexpr int WC  = DOUT / 32;     // warp-cols (4 or 2)
    constexpr int WR  = 8 / WC;        // warp-rows (2 or 4)
    constexpr int BM  = WR * 32;       // block rows (64 or 128)
    constexpr int SXH = BK + 8;        // xs half-stride (40) -> 80B rows
    constexpr int SWH = DOUT + 8;      // ws half-stride (136/72)

    const float* X = (LAYER == 0) ? Xp : g_x2;
    __half*      H = (LAYER == 0) ? g_hs : g_hs2;

    __shared__ __align__(16) __half xs_h[BM * SXH];
    __shared__ __align__(16) __half xs_l[BM * SXH];
    __shared__ __align__(16) __half ws_h[BK * SWH];
    __shared__ __align__(16) __half ws_l[BK * SWH];

    int t    = threadIdx.x;
    int w    = t >> 5;
    int lane = t & 31;
    int warpRow = w / WC;
    int warpCol = w % WC;
    int rowW0   = warpRow * 32;
    int colW0   = warpCol * 32;
    int row0    = blockIdx.x * BM;

    float acc[2][4][4];
#pragma unroll
    for (int mt = 0; mt < 2; mt++)
#pragma unroll
        for (int nt = 0; nt < 4; nt++)
#pragma unroll
            for (int q = 0; q < 4; q++) acc[mt][nt][q] = 0.f;

    // precompute ldmatrix lane addressing
    int a_row = (lane & 15);
    int a_col = (lane >> 4) * 8;
    int b_row = ((lane >> 3) & 1) * 8 + (lane & 7);
    int b_col = (lane >> 4) * 8;

    for (int kk = 0; kk < 128; kk += BK) {
        // ---- stage X chunk (split h/l)
#pragma unroll
        for (int u = 0; u < BM / 32; u++) {
            int idx = u * 256 + t;                  // BM*8 float4 slots
            int r   = idx >> 3;
            int j4  = idx & 7;
            int row = row0 + r;
            float4 x = make_float4(0.f, 0.f, 0.f, 0.f);
            if (row < N) x = *(const float4*)&X[row * 128 + kk + j4 * 4];
            uint2 hi, lo;
            split4(x, hi, lo);
            *(uint2*)&xs_h[r * SXH + j4 * 4] = hi;
            *(uint2*)&xs_l[r * SXH + j4 * 4] = lo;
        }
        // ---- stage W chunk (split h/l)
#pragma unroll
        for (int u = 0; u < DOUT / 32; u++) {
            int idx = u * 256 + t;                  // BK*DOUT/4 slots
            int k   = idx / (DOUT / 4);
            int c4  = idx % (DOUT / 4);
            float4 wv = *(const float4*)&W[(kk + k) * DOUT + c4 * 4];
            uint2 hi, lo;
            split4(wv, hi, lo);
            *(uint2*)&ws_h[k * SWH + c4 * 4] = hi;
            *(uint2*)&ws_l[k * SWH + c4 * 4] = lo;
        }
        __syncthreads();

#pragma unroll
        for (int ks = 0; ks < BK; ks += 16) {
            unsigned ah[2][4], al[2][4];
#pragma unroll
            for (int mt = 0; mt < 2; mt++) {
                int r = rowW0 + mt * 16 + a_row;
                int c = ks + a_col;
                ldm_x4(sptr(&xs_h[r * SXH + c]), ah[mt][0], ah[mt][1], ah[mt][2], ah[mt][3]);
                ldm_x4(sptr(&xs_l[r * SXH + c]), al[mt][0], al[mt][1], al[mt][2], al[mt][3]);
            }
            unsigned bh[2][4], bl[2][4];
#pragma unroll
            for (int np = 0; np < 2; np++) {
                int k = ks + b_row;
                int n = colW0 + np * 16 + b_col;
                ldm_x4t(sptr(&ws_h[k * SWH + n]), bh[np][0], bh[np][1], bh[np][2], bh[np][3]);
                ldm_x4t(sptr(&ws_l[k * SWH + n]), bl[np][0], bl[np][1], bl[np][2], bl[np][3]);
            }
#pragma unroll
            for (int mt = 0; mt < 2; mt++) {
#pragma unroll
                for (int nt = 0; nt < 4; nt++) {
                    int np = nt >> 1, hf = (nt & 1) * 2;
                    mma16816(acc[mt][nt], ah[mt], bh[np][hf], bh[np][hf + 1]);
                    mma16816(acc[mt][nt], ah[mt], bl[np][hf], bl[np][hf + 1]);
                    mma16816(acc[mt][nt], al[mt], bh[np][hf], bh[np][hf + 1]);
                }
            }
        }
        __syncthreads();
    }

    // epilogue: scale by dinv, convert fp16, store (half2 per fragment pair)
#pragma unroll
    for (int mt = 0; mt < 2; mt++) {
#pragma unroll
        for (int nt = 0; nt < 4; nt++) {
            int col = colW0 + nt * 8 + (lane & 3) * 2;
            int r0  = row0 + rowW0 + mt * 16 + (lane >> 2);
            int r1  = r0 + 8;
            if (r0 < N) {
                float s = g_dinv[r0];
                __half2 h = __floats2half2_rn(acc[mt][nt][0] * s, acc[mt][nt][1] * s);
                *(unsigned*)&H[r0 * DOUT + col] = *(unsigned*)&h;
            }
            if (r1 < N) {
                float s = g_dinv[r1];
                __half2 h = __floats2half2_rn(acc[mt][nt][2] * s, acc[mt][nt][3] * s);
                *(unsigned*)&H[r1 * DOUT + col] = *(unsigned*)&h;
            }
        }
    }
}

// ---------------------------------------------------------------------------
// Aggregate per dst node: OUT[d] = dinv[d]*(HS[d] + sum_in HS[src]) + b (+relu)
// ---------------------------------------------------------------------------
template <int DOUT, bool RELU, int LAYER>
__global__ void k_agg(const float* __restrict__ bias,
                      float* __restrict__ outp, int N)
{
    constexpr int TPN = DOUT / 8;
    constexpr int NPB = 256 / TPN;

    const __half* HS  = (LAYER == 0) ? g_hs : g_hs2;
    float*        OUT = (LAYER == 0) ? g_x2 : outp;

    int t    = threadIdx.x;
    int node = blockIdx.x * NPB + t / TPN;
    int c8   = (t % TPN) * 8;
    if (node >= N) return;

    float a[8];
    {
        uint4 v = *(const uint4*)&HS[node * DOUT + c8];
        float2 f0 = __half22float2(*(__half2*)&v.x);
        float2 f1 = __half22float2(*(__half2*)&v.y);
        float2 f2 = __half22float2(*(__half2*)&v.z);
        float2 f3 = __half22float2(*(__half2*)&v.w);
        a[0] = f0.x; a[1] = f0.y; a[2] = f1.x; a[3] = f1.y;
        a[4] = f2.x; a[5] = f2.y; a[6] = f3.x; a[7] = f3.y;
    }

    int i = g_off[node];
    int e = g_off[node + 1];
    for (; i + 4 <= e; i += 4) {
        int s0 = g_csr_src[i + 0];
        int s1 = g_csr_src[i + 1];
        int s2 = g_csr_src[i + 2];
        int s3 = g_csr_src[i + 3];
        uint4 v0 = *(const uint4*)&HS[s0 * DOUT + c8];
        uint4 v1 = *(const uint4*)&HS[s1 * DOUT + c8];
        uint4 v2 = *(const uint4*)&HS[s2 * DOUT + c8];
        uint4 v3 = *(const uint4*)&HS[s3 * DOUT + c8];
#pragma unroll
        for (int q = 0; q < 4; q++) {
            unsigned w0 = (&v0.x)[q], w1 = (&v1.x)[q],
                     w2 = (&v2.x)[q], w3 = (&v3.x)[q];
            float2 f0 = __half22float2(*(__half2*)&w0);
            float2 f1 = __half22float2(*(__half2*)&w1);
            float2 f2 = __half22float2(*(__half2*)&w2);
            float2 f3 = __half22float2(*(__half2*)&w3);
            a[2 * q]     += f0.x + f1.x + f2.x + f3.x;
            a[2 * q + 1] += f0.y + f1.y + f2.y + f3.y;
        }
    }
    for (; i < e; i++) {
        int s0 = g_csr_src[i];
        uint4 v = *(const uint4*)&HS[s0 * DOUT + c8];
#pragma unroll
        for (int q = 0; q < 4; q++) {
            unsigned w0 = (&v.x)[q];
            float2 f = __half22float2(*(__half2*)&w0);
            a[2 * q]     += f.x;
            a[2 * q + 1] += f.y;
        }
    }

    float d = g_dinv[node];
    float r[8];
#pragma unroll
    for (int q = 0; q < 8; q++) {
        float o = a[q] * d + bias[c8 + q];
        if (RELU) o = fmaxf(o, 0.f);
        r[q] = o;
    }
    float4 ob0 = make_float4(r[0], r[1], r[2], r[3]);
    float4 ob1 = make_float4(r[4], r[5], r[6], r[7]);
    *(float4*)&OUT[node * DOUT + c8]     = ob0;
    *(float4*)&OUT[node * DOUT + c8 + 4] = ob1;
}

// ---------------------------------------------------------------------------
extern "C" void kernel_launch(void* const* d_in, const int* in_sizes, int n_in,
                              void* d_out, int out_size)
{
    const float* e_prev = (const float*)d_in[0];
    const int*   ei     = (const int*)d_in[1];
    const float* W1     = (const float*)d_in[2];
    const float* b1     = (const float*)d_in[3];
    const float* W2     = (const float*)d_in[4];
    const float* b2     = (const float*)d_in[5];
    float*       out    = (float*)d_out;

    int N = in_sizes[0] / 128;   // 50000
    int E = in_sizes[1] / 2;     // 800000

    // CSR build (sequential)
    k_init <<<(N + 255) / 256, 256>>>(ei, N);
    k_hist <<<(E / 4 + 255) / 256, 256>>>(ei, E, N);
    k_scan1<<<1, 1024>>>(N, E);
    k_fill <<<(E / 4 + 255) / 256, 256>>>(ei, E, N);

    // Layer 1 (BM=64)
    k_gemm<128, 0><<<(N + 63) / 64, 256>>>(e_prev, W1, N);
    {
        constexpr int NPB = 256 / (128 / 8);
        k_agg<128, true, 0><<<(N + NPB - 1) / NPB, 256>>>(b1, nullptr, N);
    }

    // Layer 2 (BM=128)
    k_gemm<64, 1><<<(N + 127) / 128, 256>>>(nullptr, W2, N);
    {
        constexpr int NPB = 256 / (64 / 8);
        k_agg<64, false, 1><<<(N + NPB - 1) / NPB, 256>>>(b2, out, N);
    }
}